// round 15
// baseline (speedup 1.0000x reference)
#include <cuda_runtime.h>
#include <cuda_fp16.h>
#include <math.h>

#define B   2
#define NT  2048
#define DM  1024
#define H   16
#define HD  64
#define EPSF 1e-10f
#define NB_SINK 256

__device__ __half g_xh[(size_t)B*NT*DM];
__device__ __half g_Wqkvh[(size_t)3*DM*DM];
__device__ __half g_Woh[(size_t)DM*DM];
__device__ float  g_bqkv[3*DM];
__device__ __half g_Qh[(size_t)B*H*NT*HD];          // [bh][tok][hd], pre-scaled by 1/8
__device__ __half g_Kh[(size_t)B*H*NT*HD];          // [bh][tok][hd]
__device__ __half g_Vh[(size_t)B*H*NT*HD];          // [bh][hd][tok]
__device__ __half g_Eh[(size_t)B*H*NT*NT];          // exp(scores), fp16
__device__ __half g_ctxh[(size_t)B*NT*DM];
__device__ float g_P[(size_t)B*NT*NT];
__device__ float g_Z[(size_t)B*H*NT];
__device__ float g_T[(size_t)B*H*NT];
__device__ float g_Zi[(size_t)B*H*NT];
__device__ float g_u[B*NT];
__device__ float g_v[B*NT];
__device__ float g_colpart[(size_t)B*128*NT];
__device__ unsigned g_barcount = 0;
__device__ unsigned g_bargen = 0;

__device__ __forceinline__ void mma_f16(float4 &c,
    unsigned a0, unsigned a1, unsigned a2, unsigned a3,
    unsigned b0, unsigned b1)
{
    asm("mma.sync.aligned.m16n8k16.row.col.f32.f16.f16.f32 "
        "{%0,%1,%2,%3},{%4,%5,%6,%7},{%8,%9},{%0,%1,%2,%3};"
        : "+f"(c.x), "+f"(c.y), "+f"(c.z), "+f"(c.w)
        : "r"(a0), "r"(a1), "r"(a2), "r"(a3), "r"(b0), "r"(b1));
}
__device__ __forceinline__ void cp16(unsigned d, const void* s){
    asm volatile("cp.async.cg.shared.global [%0], [%1], 16;\n" :: "r"(d), "l"(s));
}
__device__ __forceinline__ void cp_commit(){ asm volatile("cp.async.commit_group;\n"); }
__device__ __forceinline__ void cp_wait1(){ asm volatile("cp.async.wait_group 1;\n" ::: "memory"); }
__device__ __forceinline__ void cp_wait0(){ asm volatile("cp.async.wait_group 0;\n" ::: "memory"); }

// ---------------------------------------------------------------------------
__global__ __launch_bounds__(256)
void cvt_all(const float* __restrict__ x,  const float* __restrict__ Wq,
             const float* __restrict__ Wk, const float* __restrict__ Wv,
             const float* __restrict__ Wo)
{
    int i = blockIdx.x * 256 + threadIdx.x;   // float4 units
    const float* src; __half* dst; int off;
    if (i < 1048576) { src = x; dst = g_xh; off = i; }
    else {
        int j = i - 1048576;
        int seg = j >> 18;
        off = j & 262143;
        src = (seg == 0) ? Wq : (seg == 1) ? Wk : (seg == 2) ? Wv : Wo;
        dst = (seg == 3) ? g_Woh : g_Wqkvh + (size_t)seg * DM * DM;
    }
    float4 v = ((const float4*)src)[off];
    ((__half2*)dst)[2*off]   = __floats2half2_rn(v.x, v.y);
    ((__half2*)dst)[2*off+1] = __floats2half2_rn(v.z, v.w);
}

__global__ __launch_bounds__(256)
void concat_bias(const float* __restrict__ bq, const float* __restrict__ bk,
                 const float* __restrict__ bv)
{
    int i = blockIdx.x * 256 + threadIdx.x;
    float v = (i < 1024) ? bq[i] : (i < 2048 ? bk[i-1024] : bv[i-2048]);
    g_bqkv[i] = v;
}

// ---------------------------------------------------------------------------
// fp16 GEMM 128x128, BK=32.  omode 0: fp32 row-major; omode 3: fused QKV
// (Q written pre-scaled by 1/8).
// ---------------------------------------------------------------------------
__global__ __launch_bounds__(256, 2)
void gemm_h(const __half* __restrict__ A, const __half* __restrict__ W,
            const float* __restrict__ bias, float* __restrict__ C,
            int N, int K, int omode)
{
    extern __shared__ __half smh[];
    __half* Asm = smh;                 // [3][128][40]
    __half* Bsm = smh + 3*128*40;
    const unsigned sA = (unsigned)__cvta_generic_to_shared(Asm);
    const unsigned sB = (unsigned)__cvta_generic_to_shared(Bsm);

    const int tid = threadIdx.x, lane = tid & 31, warp = tid >> 5;
    const int gid = lane >> 2, tig = lane & 3;
    const int wm = warp & 1, wn = warp >> 1;
    const int bm0 = blockIdx.y * 128, bn0 = blockIdx.x * 128;
    const int lr = tid >> 1, lkq = (tid & 1) * 16;
    const __half* Ag = A + (size_t)(bm0 + lr) * K + lkq;
    const __half* Wg = W + (size_t)(bn0 + lr) * K + lkq;
    const int NCH = K / 32;

    float4 acc[4][4];
    #pragma unroll
    for (int i = 0; i < 4; i++)
        #pragma unroll
        for (int j = 0; j < 4; j++) acc[i][j] = make_float4(0.f,0.f,0.f,0.f);

    auto issue = [&](int cc){
        int st = cc % 3, k0 = cc * 32;
        unsigned da = sA + (unsigned)(((st*128 + lr)*40 + lkq)*2);
        cp16(da,      Ag + k0);
        cp16(da + 16, Ag + k0 + 8);
        unsigned db = sB + (unsigned)(((st*128 + lr)*40 + lkq)*2);
        cp16(db,      Wg + k0);
        cp16(db + 16, Wg + k0 + 8);
        cp_commit();
    };

    issue(0); issue(1);

    for (int c = 0; c < NCH; c++) {
        if (c + 1 < NCH) cp_wait1(); else cp_wait0();
        __syncthreads();
        if (c + 2 < NCH) issue(c + 2);
        const __half* As_ = Asm + (c % 3)*128*40;
        const __half* Bs_ = Bsm + (c % 3)*128*40;
        #pragma unroll
        for (int ks = 0; ks < 2; ks++) {
            const int kb = ks * 16;
            unsigned af[4][4];
            #pragma unroll
            for (int mt = 0; mt < 4; mt++) {
                int m = wm*64 + mt*16 + gid;
                af[mt][0] = *(const unsigned*)&As_[m*40     + kb + 2*tig];
                af[mt][1] = *(const unsigned*)&As_[(m+8)*40 + kb + 2*tig];
                af[mt][2] = *(const unsigned*)&As_[m*40     + kb + 2*tig + 8];
                af[mt][3] = *(const unsigned*)&As_[(m+8)*40 + kb + 2*tig + 8];
            }
            #pragma unroll
            for (int nt = 0; nt < 4; nt++) {
                int n = wn*32 + nt*8 + gid;
                unsigned b0 = *(const unsigned*)&Bs_[n*40 + kb + 2*tig];
                unsigned b1 = *(const unsigned*)&Bs_[n*40 + kb + 2*tig + 8];
                #pragma unroll
                for (int mt = 0; mt < 4; mt++)
                    mma_f16(acc[mt][nt], af[mt][0],af[mt][1],af[mt][2],af[mt][3], b0, b1);
            }
        }
    }

    #pragma unroll
    for (int mt = 0; mt < 4; mt++) {
        int r0 = bm0 + wm*64 + mt*16 + gid;
        #pragma unroll
        for (int nt = 0; nt < 4; nt++) {
            int c0 = bn0 + wn*32 + nt*8 + tig*2;
            float bx, by;
            if (omode == 3) { bx = g_bqkv[c0]; by = g_bqkv[c0+1]; }
            else            { bx = bias[c0];   by = bias[c0+1];   }
            float2 lo = make_float2(acc[mt][nt].x + bx, acc[mt][nt].y + by);
            float2 hi = make_float2(acc[mt][nt].z + bx, acc[mt][nt].w + by);
            if (omode == 0) {
                float* p = C + (size_t)r0*N + c0;
                *(float2*)p = lo;
                *(float2*)(p + 8*(size_t)N) = hi;
            } else {
                int which = c0 >> 10;
                int e = c0 & 1023;
                int bb = r0 >> 11, tok = r0 & 2047, hh = e >> 6, hd = e & 63;
                size_t bh = (size_t)(bb*H + hh);
                if (which == 0) {
                    __half* p = g_Qh + (bh*NT + tok)*HD + hd;
                    *(__half2*)p          = __floats2half2_rn(lo.x*0.125f, lo.y*0.125f);
                    *(__half2*)(p + 8*HD) = __floats2half2_rn(hi.x*0.125f, hi.y*0.125f);
                } else if (which == 1) {
                    __half* p = g_Kh + (bh*NT + tok)*HD + hd;
                    *(__half2*)p          = __floats2half2_rn(lo.x, lo.y);
                    *(__half2*)(p + 8*HD) = __floats2half2_rn(hi.x, hi.y);
                } else {
                    __half* p = g_Vh + (bh*HD + hd)*NT + tok;
                    p[0]      = __float2half_rn(lo.x);
                    p[NT]     = __float2half_rn(lo.y);
                    p[8]      = __float2half_rn(hi.x);
                    p[NT + 8] = __float2half_rn(hi.y);
                }
            }
        }
    }
}

// ---------------------------------------------------------------------------
// Fused scores + exp + row Z/T/Zi.  Coalesced E stores via smem staging.
// dyn smem: pf 1KB | Qs[128][72]h | Ks[3][128][40]h | Est[128][136]h = 84992 B
// ---------------------------------------------------------------------------
__global__ __launch_bounds__(256, 2)
void scores_exp_mma(const float* __restrict__ pbs, const int* __restrict__ perm)
{
    extern __shared__ char smraw[];
    float* pfi = (float*)smraw;
    float* pfj = pfi + 128;
    __half* Qs  = (__half*)(smraw + 1024);         // [128][72]
    __half* Ks  = Qs + 128*72;                     // [3][128][40]
    __half* Est = Ks + 3*128*40;                   // [128][136]
    const unsigned sK = (unsigned)__cvta_generic_to_shared(Ks);

    const int tid = threadIdx.x, lane = tid & 31, warp = tid >> 5;
    const int gid = lane >> 2, tig = lane & 3;
    const int wm = warp & 1, wn = warp >> 1;
    const int bh = blockIdx.y, b = bh >> 4, h = bh & 15;
    const int bi0 = blockIdx.x * 128;
    const float pb = fabsf(pbs[h]);

    const __half* Qg = g_Qh + ((size_t)bh*NT + bi0)*HD;
    const __half* Kbase = g_Kh + (size_t)bh*NT*HD;
    __half* Eout = g_Eh + ((size_t)bh*NT + bi0)*NT;
    const int lr = tid >> 1;
    const int lq8 = (tid & 1) * 8;
    const int lk16 = (tid & 1) * 16;

    #pragma unroll
    for (int cq = 0; cq < 4; cq++) {
        int kk = lq8 + cq*16;
        uint4 q = *(const uint4*)(Qg + (size_t)lr*HD + kk);
        *(uint4*)&Qs[lr*72 + kk] = q;
    }
    if (tid < 128) pfi[tid] = (float)perm[b*NT + bi0 + tid] * pb;

    float Zr[8] = {0,0,0,0,0,0,0,0};
    float Tr[8] = {0,0,0,0,0,0,0,0};

    auto issue = [&](int cc){
        int st = cc % 3, jt = cc >> 1, kc = (cc & 1) * 32;
        unsigned d = sK + (unsigned)(((st*128 + lr)*40 + lk16)*2);
        const __half* s = Kbase + (size_t)(jt*128 + lr)*HD + kc + lk16;
        cp16(d, s); cp16(d + 16, s + 8);
        cp_commit();
    };

    issue(0); issue(1);
    const int NCH = 32;

    for (int jt = 0; jt < 16; jt++) {
        const int j0 = jt * 128;
        float4 acc[4][4];
        #pragma unroll
        for (int i = 0; i < 4; i++)
            #pragma unroll
            for (int j = 0; j < 4; j++) acc[i][j] = make_float4(0.f,0.f,0.f,0.f);

        #pragma unroll
        for (int k2 = 0; k2 < 2; k2++) {
            const int c = jt*2 + k2;
            if (c + 1 < NCH) cp_wait1(); else cp_wait0();
            __syncthreads();
            if (c + 2 < NCH) issue(c + 2);
            if (k2 == 0 && tid < 128) pfj[tid] = (float)perm[b*NT + j0 + tid] * pb;
            const __half* Ks_ = Ks + (c % 3)*128*40;
            const int kc = k2 * 32;

            #pragma unroll
            for (int ks = 0; ks < 2; ks++) {
                const int kb = ks * 16;
                unsigned af[4][4];
                #pragma unroll
                for (int mt = 0; mt < 4; mt++) {
                    int m = wm*64 + mt*16 + gid;
                    af[mt][0] = *(const unsigned*)&Qs[m*72     + kc + kb + 2*tig];
                    af[mt][1] = *(const unsigned*)&Qs[(m+8)*72 + kc + kb + 2*tig];
                    af[mt][2] = *(const unsigned*)&Qs[m*72     + kc + kb + 2*tig + 8];
                    af[mt][3] = *(const unsigned*)&Qs[(m+8)*72 + kc + kb + 2*tig + 8];
                }
                #pragma unroll
                for (int nt = 0; nt < 4; nt++) {
                    int n = wn*32 + nt*8 + gid;
                    unsigned b0 = *(const unsigned*)&Ks_[n*40 + kb + 2*tig];
                    unsigned b1 = *(const unsigned*)&Ks_[n*40 + kb + 2*tig + 8];
                    #pragma unroll
                    for (int mt = 0; mt < 4; mt++)
                        mma_f16(acc[mt][nt], af[mt][0],af[mt][1],af[mt][2],af[mt][3], b0, b1);
                }
            }
        }

        // epilogue: exp + Z/T accumulation; stage exp tile into Est
        #pragma unroll
        for (int mt = 0; mt < 4; mt++) {
            int rl = wm*64 + mt*16 + gid;
            float pa = pfi[rl], pc = pfi[rl+8];
            #pragma unroll
            for (int nt = 0; nt < 4; nt++) {
                int cl = wn*32 + nt*8 + tig*2;
                float d0 = pfj[cl], d1 = pfj[cl+1];
                float4 a = acc[mt][nt];
                float s00 = a.x - fabsf(pa - d0);
                float s01 = a.y - fabsf(pa - d1);
                float s10 = a.z - fabsf(pc - d0);
                float s11 = a.w - fabsf(pc - d1);
                __half2 hA = __floats2half2_rn(__expf(s00), __expf(s01));
                __half2 hB = __floats2half2_rn(__expf(s10), __expf(s11));
                float2 fA = __half22float2(hA);
                float2 fB = __half22float2(hB);
                Zr[mt*2]   += fA.x + fA.y;  Tr[mt*2]   += s00*fA.x + s01*fA.y;
                Zr[mt*2+1] += fB.x + fB.y;  Tr[mt*2+1] += s10*fB.x + s11*fB.y;
                *(__half2*)&Est[rl*136 + cl]     = hA;
                *(__half2*)&Est[(rl+8)*136 + cl] = hB;
            }
        }
        __syncthreads();
        // coalesced copy Est -> global (16B per thread per chunk)
        #pragma unroll
        for (int k = 0; k < 8; k++) {
            int chunk = tid + k*256;         // 0..2047
            int row = chunk >> 4;            // 0..127
            int off = (chunk & 15) * 8;      // halves
            uint4 v = *(const uint4*)&Est[row*136 + off];
            *(uint4*)(Eout + (size_t)row*NT + j0 + off) = v;
        }
        // Est reuse protected by next tile's first cp_wait+sync
    }

    float* redZ = (float*)Est;
    float* redT = redZ + 2048;
    const int pcol = wn*4 + tig;
    __syncthreads();
    #pragma unroll
    for (int mt = 0; mt < 4; mt++) {
        int r0 = wm*64 + mt*16 + gid;
        redZ[pcol*128 + r0]     = Zr[mt*2];
        redZ[pcol*128 + r0 + 8] = Zr[mt*2+1];
        redT[pcol*128 + r0]     = Tr[mt*2];
        redT[pcol*128 + r0 + 8] = Tr[mt*2+1];
    }
    __syncthreads();
    if (tid < 128) {
        float sz = 0.f, st = 0.f;
        #pragma unroll
        for (int t = 0; t < 16; t++) { sz += redZ[t*128 + tid]; st += redT[t*128 + tid]; }
        g_Z[(size_t)bh*NT + bi0 + tid]  = sz;
        g_Zi[(size_t)bh*NT + bi0 + tid] = 1.0f / sz;
        g_T[(size_t)bh*NT + bi0 + tid]  = st;
    }
}

// ---------------------------------------------------------------------------
// ctx(half) = (E @ V) / Z.  fp16 mma; BK=32; 3 CTAs/SM.
// ---------------------------------------------------------------------------
__global__ __launch_bounds__(256, 3)
void av_mma()
{
    __shared__ __half Es[3][128][40];
    __shared__ __half Vs[3][64][40];
    __shared__ float zin[128];
    const unsigned sE = (unsigned)__cvta_generic_to_shared(&Es[0][0][0]);
    const unsigned sV = (unsigned)__cvta_generic_to_shared(&Vs[0][0][0]);

    const int tid = threadIdx.x, lane = tid & 31, warp = tid >> 5;
    const int gid = lane >> 2, tig = lane & 3;
    const int wm = warp >> 1, wn = warp & 1;
    const int bh = blockIdx.y, b = bh >> 4, h = bh & 15;
    const int bi0 = blockIdx.x * 128;

    const int lr = tid >> 1, lk16 = (tid & 1) * 16;
    const __half* Eg = g_Eh + ((size_t)bh*NT + bi0 + lr)*NT + lk16;
    const __half* Vg = g_Vh + (size_t)bh*HD*NT;
    const int vr = (tid & 127) >> 1;

    if (tid < 128) zin[tid] = g_Zi[(size_t)bh*NT + bi0 + tid];

    float4 acc[2][4];
    #pragma unroll
    for (int i = 0; i < 2; i++)
        #pragma unroll
        for (int j = 0; j < 4; j++) acc[i][j] = make_float4(0.f,0.f,0.f,0.f);

    auto issue = [&](int cc){
        int st = cc % 3, k0 = cc * 32;
        unsigned dE = sE + (unsigned)(((st*128 + lr)*40 + lk16)*2);
        cp16(dE,      Eg + k0);
        cp16(dE + 16, Eg + k0 + 8);
        if (tid < 128) {
            unsigned dV = sV + (unsigned)(((st*64 + vr)*40 + lk16)*2);
            const __half* s = Vg + (size_t)vr*NT + k0 + lk16;
            cp16(dV, s); cp16(dV + 16, s + 8);
        }
        cp_commit();
    };

    issue(0); issue(1);
    const int NCH = NT / 32;   // 64

    for (int c = 0; c < NCH; c++) {
        if (c + 1 < NCH) cp_wait1(); else cp_wait0();
        __syncthreads();
        if (c + 2 < NCH) issue(c + 2);
        const __half* Es_ = &Es[c % 3][0][0];
        const __half* Vs_ = &Vs[c % 3][0][0];

        #pragma unroll
        for (int ks = 0; ks < 2; ks++) {
            const int kb = ks * 16;
            unsigned af[2][4];
            #pragma unroll
            for (int mt = 0; mt < 2; mt++) {
                int m = wm*32 + mt*16 + gid;
                af[mt][0] = *(const unsigned*)&Es_[m*40     + kb + 2*tig];
                af[mt][1] = *(const unsigned*)&Es_[(m+8)*40 + kb + 2*tig];
                af[mt][2] = *(const unsigned*)&Es_[m*40     + kb + 2*tig + 8];
                af[mt][3] = *(const unsigned*)&Es_[(m+8)*40 + kb + 2*tig + 8];
            }
            #pragma unroll
            for (int nt = 0; nt < 4; nt++) {
                int n = wn*32 + nt*8 + gid;
                unsigned b0 = *(const unsigned*)&Vs_[n*40 + kb + 2*tig];
                unsigned b1 = *(const unsigned*)&Vs_[n*40 + kb + 2*tig + 8];
                #pragma unroll
                for (int mt = 0; mt < 2; mt++)
                    mma_f16(acc[mt][nt], af[mt][0],af[mt][1],af[mt][2],af[mt][3], b0, b1);
            }
        }
    }

    #pragma unroll
    for (int mt = 0; mt < 2; mt++) {
        int rl = wm*32 + mt*16 + gid;
        float z0 = zin[rl], z1 = zin[rl+8];
        #pragma unroll
        for (int nt = 0; nt < 4; nt++) {
            int cl = wn*32 + nt*8 + tig*2;
            float4 a = acc[mt][nt];
            size_t base = ((size_t)b*NT + bi0 + rl)*DM + h*HD + cl;
            *(__half2*)(g_ctxh + base)        = __floats2half2_rn(a.x*z0, a.y*z0);
            *(__half2*)(g_ctxh + base + 8*DM) = __floats2half2_rn(a.z*z1, a.w*z1);
        }
    }
}

// ---------------------------------------------------------------------------
__global__ __launch_bounds__(256)
void build_P_kernel()
{
    size_t idx8 = ((size_t)blockIdx.x * 256 + threadIdx.x) * 8;
    size_t b = idx8 / ((size_t)NT*NT);
    size_t rem = idx8 - b * (size_t)NT*NT;
    int i = (int)(rem >> 11);
    float s[8] = {0,0,0,0,0,0,0,0};
    #pragma unroll
    for (int h = 0; h < H; h++) {
        const uint4* src = (const uint4*)&g_Eh[(size_t)(b*H + h)*NT*NT + rem];
        uint4 raw = __ldcg(src);
        float zi = g_Zi[(size_t)(b*H + h)*NT + i];
        float2 p0 = __half22float2(*(__half2*)&raw.x);
        float2 p1 = __half22float2(*(__half2*)&raw.y);
        float2 p2 = __half22float2(*(__half2*)&raw.z);
        float2 p3 = __half22float2(*(__half2*)&raw.w);
        s[0] += p0.x*zi; s[1] += p0.y*zi; s[2] += p1.x*zi; s[3] += p1.y*zi;
        s[4] += p2.x*zi; s[5] += p2.y*zi; s[6] += p3.x*zi; s[7] += p3.y*zi;
    }
    float o[8];
    #pragma unroll
    for (int k = 0; k < 8; k++)
        o[k] = expf(logf(s[k] * (1.0f/16.0f) + EPSF) * 10.0f);
    *(float4*)&g_P[idx8]     = make_float4(o[0],o[1],o[2],o[3]);
    *(float4*)&g_P[idx8 + 4] = make_float4(o[4],o[5],o[6],o[7]);
}

// ---------------------------------------------------------------------------
__device__ __forceinline__ void grid_sync(unsigned &gen)
{
    __syncthreads();
    if (threadIdx.x == 0) {
        gen++;
        __threadfence();
        unsigned old = atomicAdd(&g_barcount, 1);
        if (old == NB_SINK - 1) {
            atomicExch(&g_barcount, 0);
            atomicExch(&g_bargen, gen);
        } else {
            while (*(volatile unsigned*)&g_bargen < gen) __nanosleep(64);
        }
    }
    __syncthreads();
}

__global__ __launch_bounds__(256)
void sinkhorn_persist(const int* __restrict__ perm, float* __restrict__ outp)
{
    __shared__ float sv[NT];
    __shared__ float su[16];
    __shared__ float red[256];
    const int tid = threadIdx.x, bk = blockIdx.x;
    const int lane = tid & 31, w = tid >> 5;
    unsigned gen = *(volatile unsigned*)&g_bargen;

    const int row0 = bk * 16;
    const int bb = row0 >> 11;
    const int blkb = bk & 127;
    const int jbase = blkb * 16;
    float* cp = g_colpart + ((size_t)bb*128 + blkb)*NT;

    if (tid < 16) {
        su[tid] = 1.0f;
        __stcg(&g_v[bb*NT + jbase + tid], 1.0f);
    }
    grid_sync(gen);

    for (int it = 0; it < 10; it++) {
        for (int j = tid; j < NT; j += 256) sv[j] = __ldcg(&g_v[bb*NT + j]);
        __syncthreads();
        #pragma unroll
        for (int rr = 0; rr < 2; rr++) {
            int rl = w*2 + rr;
            const float* Pr = g_P + (size_t)(row0 + rl)*NT;
            float s = 0.f;
            #pragma unroll 8
            for (int j = lane; j < NT; j += 32) s += Pr[j] * sv[j];
            #pragma unroll
            for (int o = 16; o > 0; o >>= 1) s += __shfl_xor_sync(0xffffffffu, s, o);
            if (lane == 0) { float u = su[rl]; su[rl] = u / (u * s + EPSF); }
        }
        __syncthreads();
        float pa[8] = {0,0,0,0,0,0,0,0};
        #pragma unroll
        for (int i = 0; i < 16; i++) {
            float ui = su[i];
            const float* Pr = g_P + (size_t)(row0 + i)*NT;
            #pragma unroll
            for (int k = 0; k < 8; k++) pa[k] += ui * Pr[tid + k*256];
        }
        #pragma unroll
        for (int k = 0; k < 8; k++) cp[tid + k*256] = pa[k];
        grid_sync(gen);
        {
            int c = tid & 15, grp = tid >> 4;
            const float* base = g_colpart + (size_t)bb*128*NT + jbase + c;
            float s = 0.f;
            #pragma unroll
            for (int kk = 0; kk < 8; kk++)
                s += __ldcg(&base[(size_t)(grp*8 + kk)*NT]);
            red[tid] = s; __syncthreads();
            if (tid < 128) red[tid] += red[tid+128];
            __syncthreads();
            if (tid < 64)  red[tid] += red[tid+64];
            __syncthreads();
            if (tid < 32)  red[tid] += red[tid+32];
            __syncthreads();
            if (tid < 16) {
                float tot = red[tid] + red[tid+16];
                int jj = bb*NT + jbase + tid;
                float v = __ldcg(&g_v[jj]);
                __stcg(&g_v[jj], v / (v * tot + EPSF));
            }
        }
        grid_sync(gen);
    }

    for (int j = tid; j < NT; j += 256) sv[j] = __ldcg(&g_v[bb*NT + j]);
    __syncthreads();
    #pragma unroll
    for (int rr = 0; rr < 2; rr++) {
        int r = row0 + w*2 + rr;
        const float* Pr = g_P + (size_t)r * NT;
        float best = -INFINITY; int bj = NT;
        for (int j = lane; j < NT; j += 32) {
            float val = Pr[j] * sv[j];
            if (val > best) { best = val; bj = j; }
        }
        #pragma unroll
        for (int o = 16; o > 0; o >>= 1) {
            float ob = __shfl_xor_sync(0xffffffffu, best, o);
            int   oj = __shfl_xor_sync(0xffffffffu, bj, o);
            if (ob > best || (ob == best && oj < bj)) { best = ob; bj = oj; }
        }
        if (lane == 0) outp[r] = (float)perm[bb*NT + bj];
    }
}

// ---------------------------------------------------------------------------
__global__ __launch_bounds__(256)
void cert_kernel(const float* __restrict__ cert, const float* __restrict__ ctemp,
                 float* __restrict__ out)
{
    const int idx = blockIdx.x * 256 + threadIdx.x;
    const int b = idx >> 11, i = idx & 2047;
    float s = 0.f;
    #pragma unroll
    for (int h = 0; h < H; h++) {
        size_t o = (size_t)(b*H + h)*NT + i;
        float Z = g_Z[o];
        s += logf(Z) - g_T[o] / Z;
    }
    float ent = s * (1.0f / 16.0f);
    float z = ctemp[0] * (logf(2048.0f) - ent);
    out[idx] = fmaxf(cert[idx], 1.0f / (1.0f + expf(-z)));
}

extern "C" void kernel_launch(void* const* d_in, const int* in_sizes, int n_in,
                              void* d_out, int out_size)
{
    const float* x     = (const float*)d_in[0];
    const float* cert  = (const float*)d_in[1];
    const int*   perm  = (const int*)  d_in[2];
    const float* Wq    = (const float*)d_in[3];
    const float* bq    = (const float*)d_in[4];
    const float* Wk    = (const float*)d_in[5];
    const float* bk    = (const float*)d_in[6];
    const float* Wv    = (const float*)d_in[7];
    const float* bvv   = (const float*)d_in[8];
    const float* Wo    = (const float*)d_in[9];
    const float* bo    = (const float*)d_in[10];
    const float* pbs   = (const float*)d_in[11];
    const float* ctemp = (const float*)d_in[12];
    float* out = (float*)d_out;

    __half *pxh, *pWqkv, *pWoh, *pCtx;
    cudaGetSymbolAddress((void**)&pxh,   g_xh);
    cudaGetSymbolAddress((void**)&pWqkv, g_Wqkvh);
    cudaGetSymbolAddress((void**)&pWoh,  g_Woh);
    cudaGetSymbolAddress((void**)&pCtx,  g_ctxh);

    const int SMEM_H = 2*3*128*40*2;                              // 61440 B
    const int SMEM_S = 1024 + 128*72*2 + 3*128*40*2 + 128*136*2;  // 84992 B
    cudaFuncSetAttribute(gemm_h, cudaFuncAttributeMaxDynamicSharedMemorySize, SMEM_H);
    cudaFuncSetAttribute(scores_exp_mma, cudaFuncAttributeMaxDynamicSharedMemorySize, SMEM_S);

    const int M = B * NT;                  // 4096

    static cudaStream_t s2 = nullptr;
    static cudaEvent_t evFork = nullptr, evJoin = nullptr;
    if (s2 == nullptr) {
        cudaStreamCreateWithFlags(&s2, cudaStreamNonBlocking);
        cudaEventCreateWithFlags(&evFork, cudaEventDisableTiming);
        cudaEventCreateWithFlags(&evJoin, cudaEventDisableTiming);
    }

    cvt_all<<<8192, 256>>>(x, Wq, Wk, Wv, Wo);
    concat_bias<<<12, 256>>>(bq, bk, bvv);

    dim3 gQKV(3*DM/128, M/128);
    gemm_h<<<gQKV, 256, SMEM_H>>>(pxh, pWqkv, nullptr, nullptr, 3*DM, DM, 3);

    dim3 gS(NT/128, B*H);
    scores_exp_mma<<<gS, 256, SMEM_S>>>(pbs, perm);

    // fork: branch B (cert, build_P -> sinkhorn) on s2
    cudaEventRecord(evFork, 0);
    cudaStreamWaitEvent(s2, evFork, 0);
    cert_kernel<<<(B*NT)/256, 256, 0, s2>>>(cert, ctemp, out + (size_t)M*DM);
    build_P_kernel<<<4096, 256, 0, s2>>>();
    sinkhorn_persist<<<NB_SINK, 256, 0, s2>>>(perm, out + (size_t)M*DM + B*NT);
    cudaEventRecord(evJoin, s2);

    // branch A (av -> out projection) on main stream
    av_mma<<<gS, 256>>>();
    dim3 gO(DM/128, M/128);
    gemm_h<<<gO, 256, SMEM_H>>>(pCtx, pWoh, bo, out, DM, DM, 0);

    cudaStreamWaitEvent(0, evJoin, 0);
}

// round 16
// speedup vs baseline: 1.0094x; 1.0094x over previous
#include <cuda_runtime.h>
#include <cuda_fp16.h>
#include <math.h>

#define B   2
#define NT  2048
#define DM  1024
#define H   16
#define HD  64
#define EPSF 1e-10f
#define NB_SINK 256

__device__ __half g_xh[(size_t)B*NT*DM];
__device__ __half g_Wqkvh[(size_t)3*DM*DM];
__device__ __half g_Woh[(size_t)DM*DM];
__device__ float  g_bqkv[3*DM];
__device__ __half g_Qh[(size_t)B*H*NT*HD];          // [bh][tok][hd], pre-scaled by 1/8
__device__ __half g_Kh[(size_t)B*H*NT*HD];          // [bh][tok][hd]
__device__ __half g_Vh[(size_t)B*H*NT*HD];          // [bh][hd][tok]
__device__ __half g_Eh[(size_t)B*H*NT*NT];          // exp(scores), fp16
__device__ __half g_ctxh[(size_t)B*NT*DM];
__device__ float g_P[(size_t)B*NT*NT];
__device__ float g_Z[(size_t)B*H*NT];
__device__ float g_T[(size_t)B*H*NT];
__device__ float g_Zi[(size_t)B*H*NT];
__device__ float g_u[B*NT];
__device__ float g_v[B*NT];
__device__ float g_colpart[(size_t)B*128*NT];
__device__ unsigned g_barcount = 0;
__device__ unsigned g_bargen = 0;

__device__ __forceinline__ void mma_f16(float4 &c,
    unsigned a0, unsigned a1, unsigned a2, unsigned a3,
    unsigned b0, unsigned b1)
{
    asm("mma.sync.aligned.m16n8k16.row.col.f32.f16.f16.f32 "
        "{%0,%1,%2,%3},{%4,%5,%6,%7},{%8,%9},{%0,%1,%2,%3};"
        : "+f"(c.x), "+f"(c.y), "+f"(c.z), "+f"(c.w)
        : "r"(a0), "r"(a1), "r"(a2), "r"(a3), "r"(b0), "r"(b1));
}
__device__ __forceinline__ void cp16(unsigned d, const void* s){
    asm volatile("cp.async.cg.shared.global [%0], [%1], 16;\n" :: "r"(d), "l"(s));
}
__device__ __forceinline__ void cp_commit(){ asm volatile("cp.async.commit_group;\n"); }
__device__ __forceinline__ void cp_wait1(){ asm volatile("cp.async.wait_group 1;\n" ::: "memory"); }
__device__ __forceinline__ void cp_wait0(){ asm volatile("cp.async.wait_group 0;\n" ::: "memory"); }

// ---------------------------------------------------------------------------
__global__ __launch_bounds__(256)
void cvt_all(const float* __restrict__ x,  const float* __restrict__ Wq,
             const float* __restrict__ Wk, const float* __restrict__ Wv,
             const float* __restrict__ Wo)
{
    int i = blockIdx.x * 256 + threadIdx.x;   // float4 units
    const float* src; __half* dst; int off;
    if (i < 1048576) { src = x; dst = g_xh; off = i; }
    else {
        int j = i - 1048576;
        int seg = j >> 18;
        off = j & 262143;
        src = (seg == 0) ? Wq : (seg == 1) ? Wk : (seg == 2) ? Wv : Wo;
        dst = (seg == 3) ? g_Woh : g_Wqkvh + (size_t)seg * DM * DM;
    }
    float4 v = ((const float4*)src)[off];
    ((__half2*)dst)[2*off]   = __floats2half2_rn(v.x, v.y);
    ((__half2*)dst)[2*off+1] = __floats2half2_rn(v.z, v.w);
}

__global__ __launch_bounds__(256)
void concat_bias(const float* __restrict__ bq, const float* __restrict__ bk,
                 const float* __restrict__ bv)
{
    int i = blockIdx.x * 256 + threadIdx.x;
    float v = (i < 1024) ? bq[i] : (i < 2048 ? bk[i-1024] : bv[i-2048]);
    g_bqkv[i] = v;
}

// ---------------------------------------------------------------------------
// fp16 GEMM 128x128, BK=32.  omode 0: fp32 row-major; omode 3: fused QKV
// (Q written pre-scaled by 1/8).
// ---------------------------------------------------------------------------
__global__ __launch_bounds__(256, 2)
void gemm_h(const __half* __restrict__ A, const __half* __restrict__ W,
            const float* __restrict__ bias, float* __restrict__ C,
            int N, int K, int omode)
{
    extern __shared__ __half smh[];
    __half* Asm = smh;                 // [3][128][40]
    __half* Bsm = smh + 3*128*40;
    const unsigned sA = (unsigned)__cvta_generic_to_shared(Asm);
    const unsigned sB = (unsigned)__cvta_generic_to_shared(Bsm);

    const int tid = threadIdx.x, lane = tid & 31, warp = tid >> 5;
    const int gid = lane >> 2, tig = lane & 3;
    const int wm = warp & 1, wn = warp >> 1;
    const int bm0 = blockIdx.y * 128, bn0 = blockIdx.x * 128;
    const int lr = tid >> 1, lkq = (tid & 1) * 16;
    const __half* Ag = A + (size_t)(bm0 + lr) * K + lkq;
    const __half* Wg = W + (size_t)(bn0 + lr) * K + lkq;
    const int NCH = K / 32;

    float4 acc[4][4];
    #pragma unroll
    for (int i = 0; i < 4; i++)
        #pragma unroll
        for (int j = 0; j < 4; j++) acc[i][j] = make_float4(0.f,0.f,0.f,0.f);

    auto issue = [&](int cc){
        int st = cc % 3, k0 = cc * 32;
        unsigned da = sA + (unsigned)(((st*128 + lr)*40 + lkq)*2);
        cp16(da,      Ag + k0);
        cp16(da + 16, Ag + k0 + 8);
        unsigned db = sB + (unsigned)(((st*128 + lr)*40 + lkq)*2);
        cp16(db,      Wg + k0);
        cp16(db + 16, Wg + k0 + 8);
        cp_commit();
    };

    issue(0); issue(1);

    for (int c = 0; c < NCH; c++) {
        if (c + 1 < NCH) cp_wait1(); else cp_wait0();
        __syncthreads();
        if (c + 2 < NCH) issue(c + 2);
        const __half* As_ = Asm + (c % 3)*128*40;
        const __half* Bs_ = Bsm + (c % 3)*128*40;
        #pragma unroll
        for (int ks = 0; ks < 2; ks++) {
            const int kb = ks * 16;
            unsigned af[4][4];
            #pragma unroll
            for (int mt = 0; mt < 4; mt++) {
                int m = wm*64 + mt*16 + gid;
                af[mt][0] = *(const unsigned*)&As_[m*40     + kb + 2*tig];
                af[mt][1] = *(const unsigned*)&As_[(m+8)*40 + kb + 2*tig];
                af[mt][2] = *(const unsigned*)&As_[m*40     + kb + 2*tig + 8];
                af[mt][3] = *(const unsigned*)&As_[(m+8)*40 + kb + 2*tig + 8];
            }
            #pragma unroll
            for (int nt = 0; nt < 4; nt++) {
                int n = wn*32 + nt*8 + gid;
                unsigned b0 = *(const unsigned*)&Bs_[n*40 + kb + 2*tig];
                unsigned b1 = *(const unsigned*)&Bs_[n*40 + kb + 2*tig + 8];
                #pragma unroll
                for (int mt = 0; mt < 4; mt++)
                    mma_f16(acc[mt][nt], af[mt][0],af[mt][1],af[mt][2],af[mt][3], b0, b1);
            }
        }
    }

    #pragma unroll
    for (int mt = 0; mt < 4; mt++) {
        int r0 = bm0 + wm*64 + mt*16 + gid;
        #pragma unroll
        for (int nt = 0; nt < 4; nt++) {
            int c0 = bn0 + wn*32 + nt*8 + tig*2;
            float bx, by;
            if (omode == 3) { bx = g_bqkv[c0]; by = g_bqkv[c0+1]; }
            else            { bx = bias[c0];   by = bias[c0+1];   }
            float2 lo = make_float2(acc[mt][nt].x + bx, acc[mt][nt].y + by);
            float2 hi = make_float2(acc[mt][nt].z + bx, acc[mt][nt].w + by);
            if (omode == 0) {
                float* p = C + (size_t)r0*N + c0;
                *(float2*)p = lo;
                *(float2*)(p + 8*(size_t)N) = hi;
            } else {
                int which = c0 >> 10;
                int e = c0 & 1023;
                int bb = r0 >> 11, tok = r0 & 2047, hh = e >> 6, hd = e & 63;
                size_t bh = (size_t)(bb*H + hh);
                if (which == 0) {
                    __half* p = g_Qh + (bh*NT + tok)*HD + hd;
                    *(__half2*)p          = __floats2half2_rn(lo.x*0.125f, lo.y*0.125f);
                    *(__half2*)(p + 8*HD) = __floats2half2_rn(hi.x*0.125f, hi.y*0.125f);
                } else if (which == 1) {
                    __half* p = g_Kh + (bh*NT + tok)*HD + hd;
                    *(__half2*)p          = __floats2half2_rn(lo.x, lo.y);
                    *(__half2*)(p + 8*HD) = __floats2half2_rn(hi.x, hi.y);
                } else {
                    __half* p = g_Vh + (bh*HD + hd)*NT + tok;
                    p[0]      = __float2half_rn(lo.x);
                    p[NT]     = __float2half_rn(lo.y);
                    p[8]      = __float2half_rn(hi.x);
                    p[NT + 8] = __float2half_rn(hi.y);
                }
            }
        }
    }
}

// ---------------------------------------------------------------------------
// Fused scores + exp + E store + Z/T/Zi + (E@V)/Z, flash-style.
// 8 warps x 16 rows; each warp owns full 128-col stripes, so AV accumulates
// per-warp in registers with P fragments fed straight from the exp epilogue.
// dyn smem: pf 1KB | Qs[128][72]h | Ks[3][128][40]h | Vs[2][64][136]h = 84992 B
// ---------------------------------------------------------------------------
__global__ __launch_bounds__(256)
void attn_fused(const float* __restrict__ pbs, const int* __restrict__ perm)
{
    extern __shared__ char smraw[];
    float* pfi = (float*)smraw;
    float* pfj = pfi + 128;
    __half* Qs = (__half*)(smraw + 1024);          // [128][72]
    __half* Ks = Qs + 128*72;                      // [3][128][40]
    __half* Vs = Ks + 3*128*40;                    // [2][64][136]
    const unsigned sK = (unsigned)__cvta_generic_to_shared(Ks);
    const unsigned sV = (unsigned)__cvta_generic_to_shared(Vs);

    const int tid = threadIdx.x, lane = tid & 31, w = tid >> 5;
    const int gid = lane >> 2, tig = lane & 3;
    const int bh = blockIdx.y, b = bh >> 4, h = bh & 15;
    const int bi0 = blockIdx.x * 128;
    const float pb = fabsf(pbs[h]);

    const __half* Qg = g_Qh + ((size_t)bh*NT + bi0)*HD;
    const __half* Kbase = g_Kh + (size_t)bh*NT*HD;
    const __half* Vg = g_Vh + (size_t)bh*HD*NT;    // [hd][tok]
    __half* Eout = g_Eh + ((size_t)bh*NT + bi0)*NT;

    const int lr = tid >> 1;
    const int lq8 = (tid & 1) * 8;
    const int lk16 = (tid & 1) * 16;

    #pragma unroll
    for (int cq = 0; cq < 4; cq++) {
        int kk = lq8 + cq*16;
        uint4 q = *(const uint4*)(Qg + (size_t)lr*HD + kk);
        *(uint4*)&Qs[lr*72 + kk] = q;
    }
    if (tid < 128) pfi[tid] = (float)perm[b*NT + bi0 + tid] * pb;

    float Z0 = 0.f, Z1 = 0.f, T0 = 0.f, T1 = 0.f;
    float4 acc_av[8];
    #pragma unroll
    for (int i = 0; i < 8; i++) acc_av[i] = make_float4(0.f,0.f,0.f,0.f);

    // V-load mapping: per chunk, thread loads 2x cp16 of V (32 hd rows x 128 cols)
    const int vhd = tid >> 3;            // 0..31 (+ half*32)
    const int vcs = (tid & 7) * 16;      // col segment base

    auto issue = [&](int cc){
        int st = cc % 3, jt = cc >> 1, kc = (cc & 1) * 32;
        unsigned d = sK + (unsigned)(((st*128 + lr)*40 + lk16)*2);
        const __half* s = Kbase + (size_t)(jt*128 + lr)*HD + kc + lk16;
        cp16(d, s); cp16(d + 16, s + 8);
        // V half-tile: chunk c loads hd rows [(c&1)*32, +32) of V tile jt
        int hr = (cc & 1)*32 + vhd;
        unsigned dv = sV + (unsigned)((((jt & 1)*64 + hr)*136 + vcs)*2);
        const __half* sv = Vg + (size_t)hr*NT + jt*128 + vcs;
        cp16(dv, sv); cp16(dv + 16, sv + 8);
        cp_commit();
    };

    issue(0); issue(1);
    const int NCH = 32;
    const int rl = w*16 + gid;

    for (int jt = 0; jt < 16; jt++) {
        const int j0 = jt * 128;
        float4 acc[16];
        #pragma unroll
        for (int i = 0; i < 16; i++) acc[i] = make_float4(0.f,0.f,0.f,0.f);

        #pragma unroll
        for (int k2 = 0; k2 < 2; k2++) {
            const int c = jt*2 + k2;
            if (c + 1 < NCH) cp_wait1(); else cp_wait0();
            __syncthreads();
            if (c + 2 < NCH) issue(c + 2);
            if (k2 == 0 && tid < 128) pfj[tid] = (float)perm[b*NT + j0 + tid] * pb;
            const __half* Ks_ = Ks + (c % 3)*128*40;
            const int kc = k2 * 32;

            #pragma unroll
            for (int ks = 0; ks < 2; ks++) {
                const int kb = ks * 16;
                unsigned a0 = *(const unsigned*)&Qs[rl*72     + kc + kb + 2*tig];
                unsigned a1 = *(const unsigned*)&Qs[(rl+8)*72 + kc + kb + 2*tig];
                unsigned a2 = *(const unsigned*)&Qs[rl*72     + kc + kb + 2*tig + 8];
                unsigned a3 = *(const unsigned*)&Qs[(rl+8)*72 + kc + kb + 2*tig + 8];
                #pragma unroll
                for (int nt = 0; nt < 16; nt++) {
                    int n = nt*8 + gid;
                    unsigned b0 = *(const unsigned*)&Ks_[n*40 + kb + 2*tig];
                    unsigned b1 = *(const unsigned*)&Ks_[n*40 + kb + 2*tig + 8];
                    mma_f16(acc[nt], a0, a1, a2, a3, b0, b1);
                }
            }
        }

        // epilogue: bias+exp, E store, Z/T, pack P fragments
        unsigned hA[16], hB[16];
        const float pa = pfi[rl], pc = pfi[rl+8];
        #pragma unroll
        for (int nt = 0; nt < 16; nt++) {
            int cl = nt*8 + tig*2;
            float d0 = pfj[cl], d1 = pfj[cl+1];
            float4 a = acc[nt];
            float s00 = a.x - fabsf(pa - d0);
            float s01 = a.y - fabsf(pa - d1);
            float s10 = a.z - fabsf(pc - d0);
            float s11 = a.w - fabsf(pc - d1);
            __half2 e0 = __floats2half2_rn(__expf(s00), __expf(s01));
            __half2 e1 = __floats2half2_rn(__expf(s10), __expf(s11));
            float2 f0 = __half22float2(e0);
            float2 f1 = __half22float2(e1);
            Z0 += f0.x + f0.y;  T0 += s00*f0.x + s01*f0.y;
            Z1 += f1.x + f1.y;  T1 += s10*f1.x + s11*f1.y;
            size_t base = (size_t)rl*NT + j0 + cl;
            *(__half2*)(Eout + base)        = e0;
            *(__half2*)(Eout + base + 8*NT) = e1;
            hA[nt] = *(unsigned*)&e0;
            hB[nt] = *(unsigned*)&e1;
        }

        // AV: P fragments (registers) x V tile (smem)
        const __half* Vst = Vs + (jt & 1)*64*136;
        #pragma unroll
        for (int kg = 0; kg < 8; kg++) {
            unsigned a0 = hA[2*kg],   a1 = hB[2*kg];
            unsigned a2 = hA[2*kg+1], a3 = hB[2*kg+1];
            #pragma unroll
            for (int ht = 0; ht < 8; ht++) {
                int n = ht*8 + gid;
                unsigned b0 = *(const unsigned*)&Vst[n*136 + kg*16 + 2*tig];
                unsigned b1 = *(const unsigned*)&Vst[n*136 + kg*16 + 2*tig + 8];
                mma_f16(acc_av[ht], a0, a1, a2, a3, b0, b1);
            }
        }
    }

    // reduce Z/T across the 4 tig lanes of each row-quad
    #pragma unroll
    for (int o = 1; o < 4; o <<= 1) {
        Z0 += __shfl_xor_sync(0xffffffffu, Z0, o);
        Z1 += __shfl_xor_sync(0xffffffffu, Z1, o);
        T0 += __shfl_xor_sync(0xffffffffu, T0, o);
        T1 += __shfl_xor_sync(0xffffffffu, T1, o);
    }
    float zi0 = 1.0f / Z0, zi1 = 1.0f / Z1;
    if (tig == 0) {
        size_t o0 = (size_t)bh*NT + bi0 + rl;
        g_Z[o0]      = Z0;  g_Z[o0 + 8]  = Z1;
        g_Zi[o0]     = zi0; g_Zi[o0 + 8] = zi1;
        g_T[o0]      = T0;  g_T[o0 + 8]  = T1;
    }

    // ctx = acc_av / Z
    #pragma unroll
    for (int ht = 0; ht < 8; ht++) {
        int cl = h*HD + ht*8 + tig*2;
        float4 a = acc_av[ht];
        size_t base = ((size_t)b*NT + bi0 + rl)*DM + cl;
        *(__half2*)(g_ctxh + base)        = __floats2half2_rn(a.x*zi0, a.y*zi0);
        *(__half2*)(g_ctxh + base + 8*DM) = __floats2half2_rn(a.z*zi1, a.w*zi1);
    }
}

// ---------------------------------------------------------------------------
__global__ __launch_bounds__(256)
void build_P_kernel()
{
    size_t idx8 = ((size_t)blockIdx.x * 256 + threadIdx.x) * 8;
    size_t b = idx8 / ((size_t)NT*NT);
    size_t rem = idx8 - b * (size_t)NT*NT;
    int i = (int)(rem >> 11);
    float s[8] = {0,0,0,0,0,0,0,0};
    #pragma unroll
    for (int h = 0; h < H; h++) {
        const uint4* src = (const uint4*)&g_Eh[(size_t)(b*H + h)*NT*NT + rem];
        uint4 raw = __ldcg(src);
        float zi = g_Zi[(size_t)(b*H + h)*NT + i];
        float2 p0 = __half22float2(*(__half2*)&raw.x);
        float2 p1 = __half22float2(*(__half2*)&raw.y);
        float2 p2 = __half22float2(*(__half2*)&raw.z);
        float2 p3 = __half22float2(*(__half2*)&raw.w);
        s[0] += p0.x*zi; s[1] += p0.y*zi; s[2] += p1.x*zi; s[3] += p1.y*zi;
        s[4] += p2.x*zi; s[5] += p2.y*zi; s[6] += p3.x*zi; s[7] += p3.y*zi;
    }
    float o[8];
    #pragma unroll
    for (int k = 0; k < 8; k++)
        o[k] = expf(logf(s[k] * (1.0f/16.0f) + EPSF) * 10.0f);
    *(float4*)&g_P[idx8]     = make_float4(o[0],o[1],o[2],o[3]);
    *(float4*)&g_P[idx8 + 4] = make_float4(o[4],o[5],o[6],o[7]);
}

// ---------------------------------------------------------------------------
__device__ __forceinline__ void grid_sync(unsigned &gen)
{
    __syncthreads();
    if (threadIdx.x == 0) {
        gen++;
        __threadfence();
        unsigned old = atomicAdd(&g_barcount, 1);
        if (old == NB_SINK - 1) {
            atomicExch(&g_barcount, 0);
            atomicExch(&g_bargen, gen);
        } else {
            while (*(volatile unsigned*)&g_bargen < gen) __nanosleep(64);
        }
    }
    __syncthreads();
}

__global__ __launch_bounds__(256)
void sinkhorn_persist(const int* __restrict__ perm, float* __restrict__ outp)
{
    __shared__ float sv[NT];
    __shared__ float su[16];
    __shared__ float red[256];
    const int tid = threadIdx.x, bk = blockIdx.x;
    const int lane = tid & 31, w = tid >> 5;
    unsigned gen = *(volatile unsigned*)&g_bargen;

    const int row0 = bk * 16;
    const int bb = row0 >> 11;
    const int blkb = bk & 127;
    const int jbase = blkb * 16;
    float* cp = g_colpart + ((size_t)bb*128 + blkb)*NT;

    if (tid < 16) {
        su[tid] = 1.0f;
        __stcg(&g_v[bb*NT + jbase + tid], 1.0f);
    }
    grid_sync(gen);

    for (int it = 0; it < 10; it++) {
        for (int j = tid; j < NT; j += 256) sv[j] = __ldcg(&g_v[bb*NT + j]);
        __syncthreads();
        #pragma unroll
        for (int rr = 0; rr < 2; rr++) {
            int rl = w*2 + rr;
            const float* Pr = g_P + (size_t)(row0 + rl)*NT;
            float s = 0.f;
            #pragma unroll 8
            for (int j = lane; j < NT; j += 32) s += Pr[j] * sv[j];
            #pragma unroll
            for (int o = 16; o > 0; o >>= 1) s += __shfl_xor_sync(0xffffffffu, s, o);
            if (lane == 0) { float u = su[rl]; su[rl] = u / (u * s + EPSF); }
        }
        __syncthreads();
        float pa[8] = {0,0,0,0,0,0,0,0};
        #pragma unroll
        for (int i = 0; i < 16; i++) {
            float ui = su[i];
            const float* Pr = g_P + (size_t)(row0 + i)*NT;
            #pragma unroll
            for (int k = 0; k < 8; k++) pa[k] += ui * Pr[tid + k*256];
        }
        #pragma unroll
        for (int k = 0; k < 8; k++) cp[tid + k*256] = pa[k];
        grid_sync(gen);
        {
            int c = tid & 15, grp = tid >> 4;
            const float* base = g_colpart + (size_t)bb*128*NT + jbase + c;
            float s = 0.f;
            #pragma unroll
            for (int kk = 0; kk < 8; kk++)
                s += __ldcg(&base[(size_t)(grp*8 + kk)*NT]);
            red[tid] = s; __syncthreads();
            if (tid < 128) red[tid] += red[tid+128];
            __syncthreads();
            if (tid < 64)  red[tid] += red[tid+64];
            __syncthreads();
            if (tid < 32)  red[tid] += red[tid+32];
            __syncthreads();
            if (tid < 16) {
                float tot = red[tid] + red[tid+16];
                int jj = bb*NT + jbase + tid;
                float v = __ldcg(&g_v[jj]);
                __stcg(&g_v[jj], v / (v * tot + EPSF));
            }
        }
        grid_sync(gen);
    }

    for (int j = tid; j < NT; j += 256) sv[j] = __ldcg(&g_v[bb*NT + j]);
    __syncthreads();
    #pragma unroll
    for (int rr = 0; rr < 2; rr++) {
        int r = row0 + w*2 + rr;
        const float* Pr = g_P + (size_t)r * NT;
        float best = -INFINITY; int bj = NT;
        for (int j = lane; j < NT; j += 32) {
            float val = Pr[j] * sv[j];
            if (val > best) { best = val; bj = j; }
        }
        #pragma unroll
        for (int o = 16; o > 0; o >>= 1) {
            float ob = __shfl_xor_sync(0xffffffffu, best, o);
            int   oj = __shfl_xor_sync(0xffffffffu, bj, o);
            if (ob > best || (ob == best && oj < bj)) { best = ob; bj = oj; }
        }
        if (lane == 0) outp[r] = (float)perm[bb*NT + bj];
    }
}

// ---------------------------------------------------------------------------
__global__ __launch_bounds__(256)
void cert_kernel(const float* __restrict__ cert, const float* __restrict__ ctemp,
                 float* __restrict__ out)
{
    const int idx = blockIdx.x * 256 + threadIdx.x;
    const int b = idx >> 11, i = idx & 2047;
    float s = 0.f;
    #pragma unroll
    for (int h = 0; h < H; h++) {
        size_t o = (size_t)(b*H + h)*NT + i;
        float Z = g_Z[o];
        s += logf(Z) - g_T[o] / Z;
    }
    float ent = s * (1.0f / 16.0f);
    float z = ctemp[0] * (logf(2048.0f) - ent);
    out[idx] = fmaxf(cert[idx], 1.0f / (1.0f + expf(-z)));
}

extern "C" void kernel_launch(void* const* d_in, const int* in_sizes, int n_in,
                              void* d_out, int out_size)
{
    const float* x     = (const float*)d_in[0];
    const float* cert  = (const float*)d_in[1];
    const int*   perm  = (const int*)  d_in[2];
    const float* Wq    = (const float*)d_in[3];
    const float* bq    = (const float*)d_in[4];
    const float* Wk    = (const float*)d_in[5];
    const float* bk    = (const float*)d_in[6];
    const float* Wv    = (const float*)d_in[7];
    const float* bvv   = (const float*)d_in[8];
    const float* Wo    = (const float*)d_in[9];
    const float* bo    = (const float*)d_in[10];
    const float* pbs   = (const float*)d_in[11];
    const float* ctemp = (const float*)d_in[12];
    float* out = (float*)d_out;

    __half *pxh, *pWqkv, *pWoh, *pCtx;
    cudaGetSymbolAddress((void**)&pxh,   g_xh);
    cudaGetSymbolAddress((void**)&pWqkv, g_Wqkvh);
    cudaGetSymbolAddress((void**)&pWoh,  g_Woh);
    cudaGetSymbolAddress((void**)&pCtx,  g_ctxh);

    const int SMEM_H = 2*3*128*40*2;                              // 61440 B
    const int SMEM_F = 1024 + 128*72*2 + 3*128*40*2 + 2*64*136*2; // 84992 B
    cudaFuncSetAttribute(gemm_h, cudaFuncAttributeMaxDynamicSharedMemorySize, SMEM_H);
    cudaFuncSetAttribute(attn_fused, cudaFuncAttributeMaxDynamicSharedMemorySize, SMEM_F);

    const int M = B * NT;                  // 4096

    static cudaStream_t s2 = nullptr;
    static cudaEvent_t evFork = nullptr, evJoin = nullptr;
    if (s2 == nullptr) {
        cudaStreamCreateWithFlags(&s2, cudaStreamNonBlocking);
        cudaEventCreateWithFlags(&evFork, cudaEventDisableTiming);
        cudaEventCreateWithFlags(&evJoin, cudaEventDisableTiming);
    }

    cvt_all<<<8192, 256>>>(x, Wq, Wk, Wv, Wo);
    concat_bias<<<12, 256>>>(bq, bk, bvv);

    dim3 gQKV(3*DM/128, M/128);
    gemm_h<<<gQKV, 256, SMEM_H>>>(pxh, pWqkv, nullptr, nullptr, 3*DM, DM, 3);

    dim3 gS(NT/128, B*H);
    attn_fused<<<gS, 256, SMEM_F>>>(pbs, perm);

    // fork: branch B (cert, build_P -> sinkhorn) on s2
    cudaEventRecord(evFork, 0);
    cudaStreamWaitEvent(s2, evFork, 0);
    cert_kernel<<<(B*NT)/256, 256, 0, s2>>>(cert, ctemp, out + (size_t)M*DM);
    build_P_kernel<<<4096, 256, 0, s2>>>();
    sinkhorn_persist<<<NB_SINK, 256, 0, s2>>>(perm, out + (size_t)M*DM + B*NT);
    cudaEventRecord(evJoin, s2);

    // branch A: output projection on main stream
    dim3 gO(DM/128, M/128);
    gemm_h<<<gO, 256, SMEM_H>>>(pCtx, pWoh, bo, out, DM, DM, 0);

    cudaStreamWaitEvent(0, evJoin, 0);
}